// round 12
// baseline (speedup 1.0000x reference)
#include <cuda_runtime.h>
#include <cstdint>
#include <cstddef>

// Problem constants
#define N_E   1024
#define CDIM  256
#define NB    16
#define NH    64
#define NW    64
#define HW_   (NH*NW)        // 4096
#define NROWS (NB*HW_)       // 65536
#define COS_ELEMS (NB*NW*CDIM)  // 262144

// Output layout (float32): [cosine (B,W,C) | idx_gt (N) | idx (N)]
#define OFF_IDXGT COS_ELEMS
#define OFF_IDX   (COS_ELEMS + NROWS)

// Scratch (device globals: allocation-free rule)
__device__ float g_cbnorm[N_E];
__device__ float g_xnorm[2 * NROWS];
__device__ float g_bv[2][2][NROWS];   // [src][jhalf][row] partial best dist
__device__ int   g_bj[2][2][NROWS];   // [src][jhalf][row] partial best idx

// ---------- packed f32x2 helpers (sm_100+) ----------
static __device__ __forceinline__ void upk2(float& lo, float& hi, unsigned long long v) {
    asm("mov.b64 {%0,%1}, %2;" : "=f"(lo), "=f"(hi) : "l"(v));
}
static __device__ __forceinline__ void fma2(unsigned long long& d,
                                            unsigned long long a,
                                            unsigned long long b) {
    asm("fma.rn.f32x2 %0, %1, %2, %3;" : "=l"(d) : "l"(a), "l"(b), "l"(d));
}

// ---------- XLA-row-reduce-emulating sum of squares over 256 elements ----------
// (unchanged — this bracketing is what makes argmins match the reference)
template <int STRIDE>
static __device__ __forceinline__ float xla_row_sumsq(const float* __restrict__ p, int lane) {
    float T[4];
#pragma unroll
    for (int w = 0; w < 4; w++) {
        int c0 = w * 64 + 2 * lane;
        float a = p[(size_t)c0 * STRIDE];
        float b = p[(size_t)(c0 + 1) * STRIDE];
        float v = __fadd_rn(__fmul_rn(a, a), __fmul_rn(b, b));
#pragma unroll
        for (int off = 16; off > 0; off >>= 1)
            v = __fadd_rn(v, __shfl_xor_sync(0xffffffffu, v, off));
        T[w] = v;
    }
    return __fadd_rn(__fadd_rn(T[0], T[2]), __fadd_rn(T[1], T[3]));
}

// ---------- kernel 1: codebook squared norms ----------
__global__ void cbnorm_kernel(const float* __restrict__ cb) {
    int warp = blockIdx.x * (blockDim.x >> 5) + (threadIdx.x >> 5);
    int lane = threadIdx.x & 31;
    if (warp >= N_E) return;
    float s = xla_row_sumsq<1>(cb + (size_t)warp * CDIM, lane);
    if (lane == 0) g_cbnorm[warp] = s;
}

// ---------- kernel 2: per-row ||x||^2, coalesced via SMEM transpose ----------
__global__ __launch_bounds__(256)
void xnorm_kernel(const float* __restrict__ x, int src) {
    __shared__ float ts[32][257];
    const int n0  = blockIdx.x << 5;          // 2048 blocks per source
    const int b   = n0 >> 12;
    const int rem = n0 & (HW_ - 1);
    const float* base = x + (size_t)b * CDIM * HW_ + rem;
    const int w = threadIdx.x >> 5, l = threadIdx.x & 31;
#pragma unroll
    for (int i = 0; i < 32; i++) {
        int c = w + (i << 3);                 // warp w covers c = w, w+8, ...
        ts[l][c] = base[(size_t)c * HW_ + l];
    }
    __syncthreads();
#pragma unroll
    for (int r = 0; r < 4; r++) {
        int row = (w << 2) + r;
        float s = xla_row_sumsq<1>(&ts[row][0], l);
        if (l == 0) g_xnorm[src * NROWS + n0 + row] = s;
    }
}

// ---------- kernel 3: fused distance-GEMM + partial argmin ----------
// BM=128 x BN=128, K tiles of 16, 256 threads, 2 blocks/SM, jhalf split.
// B stored PRE-DUPLICATED as float2{v,v} in SMEM: each B operand is one
// LDS.64 whose dest register pair is directly the f32x2 operand (no dup2
// MOVs, no LDS->MOV->FMA chain). Per-thread j-mapping j = (e<<4)+tx makes
// the 16 lanes' 8B loads contiguous (128B, conflict-free).
// Accumulator lanes: pure ascending-k sequential fma.rn chains from 0 ->
// distances bit-identical to all previous passing rounds.
__global__ __launch_bounds__(256, 2)
void argmin_kernel(const float* __restrict__ z, const float* __restrict__ gt,
                   const float* __restrict__ cb) {
    __shared__ float4 xs4[2][16][32];     // [buf][k][row/4]  8KB per buf
    __shared__ float2 cs2[2][16][130];    // [buf][k][j] dup pairs, pad 2
    __shared__ float  cbn_s[512];         // this half's codebook norms

    const int tid = threadIdx.x;
    const int ty = tid >> 4, tx = tid & 15;          // ty: row group, tx: j lane
    const int src = blockIdx.y;                      // 0 = z, 1 = gt
    const int jh  = blockIdx.z;                      // codes [jh*512, jh*512+512)
    const int rowTile = blockIdx.x << 7;             // *128 (4096%128==0)
    const int b    = rowTile >> 12;
    const int rem0 = rowTile & (HW_ - 1);
    const float* __restrict__ x =
        (src ? gt : z) + (size_t)b * CDIM * HW_ + rem0;

#pragma unroll
    for (int i = 0; i < 2; i++)
        cbn_s[tid + (i << 8)] = g_cbnorm[(jh << 9) + tid + (i << 8)];

    float xn[8];
#pragma unroll
    for (int r = 0; r < 8; r++)
        xn[r] = g_xnorm[src * NROWS + rowTile + ty * 8 + r];

    // x-tile staging map (unchanged)
    const int k0 = tid >> 5;                  // 0..7
    const int m0 = tid & 31;
    const float* xp0 = x + (size_t)k0 * HW_ + (m0 << 2);
    const float* xp1 = x + (size_t)(k0 + 8) * HW_ + (m0 << 2);

    // cb staging map: thread loads j = jl0 (+64) at columns c4..c4+3
    const int jl0 = tid >> 2;                 // 0..63
    const int c4  = (tid & 3) << 2;           // 0,4,8,12
    const float* cbp0 = cb + (size_t)((jh << 9) + jl0) * CDIM + c4;

    __syncthreads();

    float bestv[8];
    int   bestj[8];
#pragma unroll
    for (int r = 0; r < 8; r++) { bestv[r] = 3.0e38f; bestj[r] = 0; }

    for (int jt = 0; jt < 4; jt++) {
        unsigned long long acc[4][8];
#pragma unroll
        for (int p = 0; p < 4; p++)
#pragma unroll
            for (int q = 0; q < 8; q++) acc[p][q] = 0ull;

        const float* cbp = cbp0 + (size_t)(jt * 128) * CDIM;

        // prologue: stage kt=0 into registers
        float4 xreg0 = *(const float4*)(xp0);
        float4 xreg1 = *(const float4*)(xp1);
        float4 creg0 = *(const float4*)(cbp);
        float4 creg1 = *(const float4*)(cbp + 64 * CDIM);

        for (int kt = 0; kt < 16; kt++) {
            const int buf = kt & 1;
            // commit staged registers to smem[buf]; B pre-duplicated {v,v}
            xs4[buf][k0][m0]     = xreg0;
            xs4[buf][k0 + 8][m0] = xreg1;
            cs2[buf][c4 + 0][jl0]      = make_float2(creg0.x, creg0.x);
            cs2[buf][c4 + 1][jl0]      = make_float2(creg0.y, creg0.y);
            cs2[buf][c4 + 2][jl0]      = make_float2(creg0.z, creg0.z);
            cs2[buf][c4 + 3][jl0]      = make_float2(creg0.w, creg0.w);
            cs2[buf][c4 + 0][jl0 + 64] = make_float2(creg1.x, creg1.x);
            cs2[buf][c4 + 1][jl0 + 64] = make_float2(creg1.y, creg1.y);
            cs2[buf][c4 + 2][jl0 + 64] = make_float2(creg1.z, creg1.z);
            cs2[buf][c4 + 3][jl0 + 64] = make_float2(creg1.w, creg1.w);
            __syncthreads();
            if (kt < 15) {                   // prefetch kt+1 (overlaps compute)
                const int kb = (kt + 1) * 16;
                xreg0 = *(const float4*)(xp0 + (size_t)kb * HW_);
                xreg1 = *(const float4*)(xp1 + (size_t)kb * HW_);
                creg0 = *(const float4*)(cbp + (size_t)(kt + 1) * 16);
                creg1 = *(const float4*)(cbp + 64 * CDIM + (size_t)(kt + 1) * 16);
            }
#pragma unroll
            for (int k = 0; k < 16; k++) {
                // A: rows 8ty..8ty+7 as 4 natural f32x2 pairs
                ulonglong2 u0 = *(const ulonglong2*)&xs4[buf][k][2 * ty];
                ulonglong2 u1 = *(const ulonglong2*)&xs4[buf][k][2 * ty + 1];
                unsigned long long av[4];
                av[0] = u0.x; av[1] = u0.y; av[2] = u1.x; av[3] = u1.y;
#pragma unroll
                for (int qq = 0; qq < 2; qq++) {
#pragma unroll
                    for (int e = 0; e < 4; e++) {
                        // j = (qq<<6)+(e<<4)+tx : lanes contiguous -> 1-phase LDS.64
                        unsigned long long bp = *(const unsigned long long*)
                            &cs2[buf][k][(qq << 6) + (e << 4) + tx];
#pragma unroll
                        for (int p = 0; p < 4; p++)
                            fma2(acc[p][(qq << 2) + e], av[p], bp);
                    }
                }
            }
        }

        // epilogue: dist = (||x||^2 + ||cb||^2) - 2*dot; running argmin.
        // Within-thread scan ascending j: qq asc, e asc.
#pragma unroll
        for (int qq = 0; qq < 2; qq++)
#pragma unroll
            for (int e = 0; e < 4; e++) {
                const int jloc = (jt << 7) + (qq << 6) + (e << 4) + tx;
                const int jg   = (jh << 9) + jloc;
                const float cbn = cbn_s[jloc];
#pragma unroll
                for (int p = 0; p < 4; p++) {
                    float d0, d1;
                    upk2(d0, d1, acc[p][(qq << 2) + e]);
                    const int r0 = 2 * p, r1 = 2 * p + 1;
                    float dist0 = (xn[r0] + cbn) - 2.0f * d0;
                    float dist1 = (xn[r1] + cbn) - 2.0f * d1;
                    if (dist0 < bestv[r0]) { bestv[r0] = dist0; bestj[r0] = jg; }
                    if (dist1 < bestv[r1]) { bestv[r1] = dist1; bestj[r1] = jg; }
                }
            }
        __syncthreads();   // protect smem[buf 15] from next jt's prologue commits
    }

    // reduce across the 16 tx lanes; tie-break: smaller j (first occurrence).
#pragma unroll
    for (int off = 1; off < 16; off <<= 1) {
#pragma unroll
        for (int r = 0; r < 8; r++) {
            float ov = __shfl_xor_sync(0xffffffffu, bestv[r], off);
            int   oj = __shfl_xor_sync(0xffffffffu, bestj[r], off);
            if (ov < bestv[r] || (ov == bestv[r] && oj < bestj[r])) {
                bestv[r] = ov; bestj[r] = oj;
            }
        }
    }
    if (tx == 0) {
#pragma unroll
        for (int r = 0; r < 8; r++) {
            g_bv[src][jh][rowTile + ty * 8 + r] = bestv[r];
            g_bj[src][jh][rowTile + ty * 8 + r] = bestj[r];
        }
    }
}

// ---------- kernel 3b: merge the two j-halves ----------
__global__ void combine_kernel(float* __restrict__ out) {
    int i = blockIdx.x * blockDim.x + threadIdx.x;   // 0..131071
    int src = i >> 16;
    int n   = i & (NROWS - 1);
    float v0 = g_bv[src][0][n];
    float v1 = g_bv[src][1][n];
    int   j  = (v1 < v0) ? g_bj[src][1][n] : g_bj[src][0][n];
    out[(src ? OFF_IDXGT : OFF_IDX) + n] = (float)j;
}

// ---------- kernel 4: gather + cosine over H (unchanged) ----------
__global__ void cosine_kernel(const float* __restrict__ cb, float* __restrict__ out) {
    int bw = blockIdx.x;          // 0..1023
    int b  = bw >> 6;
    int w  = bw & 63;
    int c  = threadIdx.x;         // 0..255
    __shared__ int i1s[64], i2s[64];
    const float* f_gt = out + OFF_IDXGT;
    const float* f_z  = out + OFF_IDX;
    if (c < 64) {
        int n = (b << 12) + (c << 6) + w;   // c plays the role of h here
        i1s[c] = (int)f_gt[n];
        i2s[c] = (int)f_z[n];
    }
    __syncthreads();
    float num = 0.f, na = 0.f, nq = 0.f;
    for (int h = 0; h < 64; h++) {
        float a = cb[(size_t)i1s[h] * CDIM + c];
        float q = cb[(size_t)i2s[h] * CDIM + c];
        num = __fadd_rn(num, __fmul_rn(a, q));
        na  = __fadd_rn(na,  __fmul_rn(a, a));
        nq  = __fadd_rn(nq,  __fmul_rn(q, q));
    }
    float nx = fmaxf(__fsqrt_rn(na), 1e-8f);
    float ny = fmaxf(__fsqrt_rn(nq), 1e-8f);
    out[(size_t)bw * CDIM + c] = __fdiv_rn(num, __fmul_rn(nx, ny));
}

extern "C" void kernel_launch(void* const* d_in, const int* in_sizes, int n_in,
                              void* d_out, int out_size) {
    const float* z  = (const float*)d_in[0];
    const float* gt = (const float*)d_in[1];
    const float* cb = (const float*)d_in[2];
    float* out = (float*)d_out;

    cbnorm_kernel<<<128, 256>>>(cb);          // launch 0
    xnorm_kernel<<<2048, 256>>>(z, 0);        // launch 1
    xnorm_kernel<<<2048, 256>>>(gt, 1);       // launch 2
    argmin_kernel<<<dim3(512, 2, 2), 256>>>(z, gt, cb);   // launch 3 (ncu samples idx 3)
    combine_kernel<<<128, 1024>>>(out);       // launch 4
    cosine_kernel<<<NB * NW, CDIM>>>(cb, out);// launch 5
}

// round 14
// speedup vs baseline: 1.0275x; 1.0275x over previous
#include <cuda_runtime.h>
#include <cstdint>
#include <cstddef>

// Problem constants
#define N_E   1024
#define CDIM  256
#define NB    16
#define NH    64
#define NW    64
#define HW_   (NH*NW)        // 4096
#define NROWS (NB*HW_)       // 65536
#define COS_ELEMS (NB*NW*CDIM)  // 262144

// Output layout (float32): [cosine (B,W,C) | idx_gt (N) | idx (N)]
#define OFF_IDXGT COS_ELEMS
#define OFF_IDX   (COS_ELEMS + NROWS)

// Scratch (device globals: allocation-free rule)
__device__ float g_cbnorm[N_E];
__device__ float g_xnorm[2 * NROWS];
__device__ float g_bv[2][2][NROWS];   // [src][jhalf][row] partial best dist
__device__ int   g_bj[2][2][NROWS];   // [src][jhalf][row] partial best idx

// ---------- packed f32x2 helpers (sm_100+) ----------
static __device__ __forceinline__ void upk2(float& lo, float& hi, unsigned long long v) {
    asm("mov.b64 {%0,%1}, %2;" : "=f"(lo), "=f"(hi) : "l"(v));
}
static __device__ __forceinline__ void fma2(unsigned long long& d,
                                            unsigned long long a,
                                            unsigned long long b) {
    asm("fma.rn.f32x2 %0, %1, %2, %3;" : "=l"(d) : "l"(a), "l"(b), "l"(d));
}

// ---------- XLA-row-reduce-emulating sum of squares over 256 elements ----------
// (unchanged — this bracketing is what makes argmins match the reference)
template <int STRIDE>
static __device__ __forceinline__ float xla_row_sumsq(const float* __restrict__ p, int lane) {
    float T[4];
#pragma unroll
    for (int w = 0; w < 4; w++) {
        int c0 = w * 64 + 2 * lane;
        float a = p[(size_t)c0 * STRIDE];
        float b = p[(size_t)(c0 + 1) * STRIDE];
        float v = __fadd_rn(__fmul_rn(a, a), __fmul_rn(b, b));
#pragma unroll
        for (int off = 16; off > 0; off >>= 1)
            v = __fadd_rn(v, __shfl_xor_sync(0xffffffffu, v, off));
        T[w] = v;
    }
    return __fadd_rn(__fadd_rn(T[0], T[2]), __fadd_rn(T[1], T[3]));
}

// ---------- kernel 1: codebook squared norms ----------
__global__ void cbnorm_kernel(const float* __restrict__ cb) {
    int warp = blockIdx.x * (blockDim.x >> 5) + (threadIdx.x >> 5);
    int lane = threadIdx.x & 31;
    if (warp >= N_E) return;
    float s = xla_row_sumsq<1>(cb + (size_t)warp * CDIM, lane);
    if (lane == 0) g_cbnorm[warp] = s;
}

// ---------- kernel 2: per-row ||x||^2, coalesced via SMEM transpose ----------
__global__ __launch_bounds__(256)
void xnorm_kernel(const float* __restrict__ x, int src) {
    __shared__ float ts[32][257];
    const int n0  = blockIdx.x << 5;          // 2048 blocks per source
    const int b   = n0 >> 12;
    const int rem = n0 & (HW_ - 1);
    const float* base = x + (size_t)b * CDIM * HW_ + rem;
    const int w = threadIdx.x >> 5, l = threadIdx.x & 31;
#pragma unroll
    for (int i = 0; i < 32; i++) {
        int c = w + (i << 3);                 // warp w covers c = w, w+8, ...
        ts[l][c] = base[(size_t)c * HW_ + l];
    }
    __syncthreads();
#pragma unroll
    for (int r = 0; r < 4; r++) {
        int row = (w << 2) + r;
        float s = xla_row_sumsq<1>(&ts[row][0], l);
        if (l == 0) g_xnorm[src * NROWS + n0 + row] = s;
    }
}

// ---------- kernel 3: fused distance-GEMM + partial argmin ----------
// BM=128 x BN=128, K tiles of 16, 256 threads, 2 blocks/SM, jhalf split.
// f32x2 packing over J-PAIRS: A pre-duplicated {v,v} in SMEM (consecutive
// rows -> 4 LDS.128 load all 8 row operands, broadcast), B natural j-pairs
// (4 LDS.64, lanes contiguous). Inner loop: 32 FMA2 + 8 LDS, ZERO MOVs.
// Register-staged depth-2 pipeline. Accumulator lanes: pure ascending-k
// sequential fma.rn chains from 0 -> distances bit-identical to all
// previous passing rounds.
__global__ __launch_bounds__(256, 2)
void argmin_kernel(const float* __restrict__ z, const float* __restrict__ gt,
                   const float* __restrict__ cb) {
    __shared__ float2 xs2[2][16][128];    // [buf][k][row] dup {v,v}  16KB/buf
    __shared__ float  cs[2][16][132];     // [buf][k][j] scalar, pad->528B rows
    __shared__ float  cbn_s[512];         // this half's codebook norms

    const int tid = threadIdx.x;
    const int ty = tid >> 4, tx = tid & 15;          // ty: row group, tx: j lane
    const int src = blockIdx.y;                      // 0 = z, 1 = gt
    const int jh  = blockIdx.z;                      // codes [jh*512, jh*512+512)
    const int rowTile = blockIdx.x << 7;             // *128 (4096%128==0)
    const int b    = rowTile >> 12;
    const int rem0 = rowTile & (HW_ - 1);
    const float* __restrict__ x =
        (src ? gt : z) + (size_t)b * CDIM * HW_ + rem0;

#pragma unroll
    for (int i = 0; i < 2; i++)
        cbn_s[tid + (i << 8)] = g_cbnorm[(jh << 9) + tid + (i << 8)];

    float xn[8];
#pragma unroll
    for (int r = 0; r < 8; r++)
        xn[r] = g_xnorm[src * NROWS + rowTile + ty * 8 + r];

    // x-tile staging map: thread stages rows m40..m40+3 for k0 and k0+8
    const int k0 = tid >> 5;                  // 0..7
    const int m40 = (tid & 31) << 2;          // row group 0..124
    const float* xp0 = x + (size_t)k0 * HW_ + m40;
    const float* xp1 = x + (size_t)(k0 + 8) * HW_ + m40;

    // cb staging map: thread loads j = jl0 (+64) at columns c4..c4+3
    const int jl0 = tid >> 2;                 // 0..63
    const int c4  = (tid & 3) << 2;           // 0,4,8,12
    const float* cbp0 = cb + (size_t)((jh << 9) + jl0) * CDIM + c4;

    __syncthreads();

    float bestv[8];
    int   bestj[8];
#pragma unroll
    for (int r = 0; r < 8; r++) { bestv[r] = 3.0e38f; bestj[r] = 0; }

    for (int jt = 0; jt < 4; jt++) {
        unsigned long long acc[8][4];          // [row][j-pair]
#pragma unroll
        for (int r = 0; r < 8; r++)
#pragma unroll
            for (int i = 0; i < 4; i++) acc[r][i] = 0ull;

        const float* cbp = cbp0 + (size_t)(jt * 128) * CDIM;

        // prologue: stage kt=0 into registers
        float4 xreg0 = *(const float4*)(xp0);
        float4 xreg1 = *(const float4*)(xp1);
        float4 creg0 = *(const float4*)(cbp);
        float4 creg1 = *(const float4*)(cbp + 64 * CDIM);

        for (int kt = 0; kt < 16; kt++) {
            const int buf = kt & 1;
            // commit staged registers to smem[buf]; A pre-duplicated {v,v}
            *(float4*)&xs2[buf][k0][m40]         = make_float4(xreg0.x, xreg0.x, xreg0.y, xreg0.y);
            *(float4*)&xs2[buf][k0][m40 + 2]     = make_float4(xreg0.z, xreg0.z, xreg0.w, xreg0.w);
            *(float4*)&xs2[buf][k0 + 8][m40]     = make_float4(xreg1.x, xreg1.x, xreg1.y, xreg1.y);
            *(float4*)&xs2[buf][k0 + 8][m40 + 2] = make_float4(xreg1.z, xreg1.z, xreg1.w, xreg1.w);
            cs[buf][c4 + 0][jl0]      = creg0.x;
            cs[buf][c4 + 1][jl0]      = creg0.y;
            cs[buf][c4 + 2][jl0]      = creg0.z;
            cs[buf][c4 + 3][jl0]      = creg0.w;
            cs[buf][c4 + 0][jl0 + 64] = creg1.x;
            cs[buf][c4 + 1][jl0 + 64] = creg1.y;
            cs[buf][c4 + 2][jl0 + 64] = creg1.z;
            cs[buf][c4 + 3][jl0 + 64] = creg1.w;
            __syncthreads();
            if (kt < 15) {                   // prefetch kt+1 (overlaps compute)
                const int kb = (kt + 1) * 16;
                xreg0 = *(const float4*)(xp0 + (size_t)kb * HW_);
                xreg1 = *(const float4*)(xp1 + (size_t)kb * HW_);
                creg0 = *(const float4*)(cbp + (size_t)(kt + 1) * 16);
                creg1 = *(const float4*)(cbp + 64 * CDIM + (size_t)(kt + 1) * 16);
            }
#pragma unroll
            for (int k = 0; k < 16; k++) {
                // A: 8 dup-row operands via 4 broadcast LDS.128
                ulonglong2 A0 = *(const ulonglong2*)&xs2[buf][k][ty * 8];
                ulonglong2 A1 = *(const ulonglong2*)&xs2[buf][k][ty * 8 + 2];
                ulonglong2 A2 = *(const ulonglong2*)&xs2[buf][k][ty * 8 + 4];
                ulonglong2 A3 = *(const ulonglong2*)&xs2[buf][k][ty * 8 + 6];
                unsigned long long av[8];
                av[0] = A0.x; av[1] = A0.y; av[2] = A1.x; av[3] = A1.y;
                av[4] = A2.x; av[5] = A2.y; av[6] = A3.x; av[7] = A3.y;
                // B: 4 natural j-pair operands via 4 contiguous LDS.64
                unsigned long long bv[4];
#pragma unroll
                for (int i = 0; i < 4; i++)
                    bv[i] = *(const unsigned long long*)&cs[buf][k][(i << 5) + (tx << 1)];
#pragma unroll
                for (int r = 0; r < 8; r++)
#pragma unroll
                    for (int i = 0; i < 4; i++)
                        fma2(acc[r][i], av[r], bv[i]);
            }
        }

        // epilogue: dist = (||x||^2 + ||cb||^2) - 2*dot; running argmin.
        // Within-thread scan ascending j: i asc, then pair-lane e asc.
#pragma unroll
        for (int i = 0; i < 4; i++) {
            const int jloc0 = (jt << 7) + (i << 5) + (tx << 1);
            const float cbn0 = cbn_s[jloc0];
            const float cbn1 = cbn_s[jloc0 + 1];
            const int jg = (jh << 9) + jloc0;
#pragma unroll
            for (int r = 0; r < 8; r++) {
                float d0, d1;
                upk2(d0, d1, acc[r][i]);
                float dist0 = (xn[r] + cbn0) - 2.0f * d0;
                float dist1 = (xn[r] + cbn1) - 2.0f * d1;
                if (dist0 < bestv[r]) { bestv[r] = dist0; bestj[r] = jg; }
                if (dist1 < bestv[r]) { bestv[r] = dist1; bestj[r] = jg + 1; }
            }
        }
        __syncthreads();   // protect smem[buf 15] from next jt's prologue commits
    }

    // reduce across the 16 tx lanes; tie-break: smaller j (first occurrence).
#pragma unroll
    for (int off = 1; off < 16; off <<= 1) {
#pragma unroll
        for (int r = 0; r < 8; r++) {
            float ov = __shfl_xor_sync(0xffffffffu, bestv[r], off);
            int   oj = __shfl_xor_sync(0xffffffffu, bestj[r], off);
            if (ov < bestv[r] || (ov == bestv[r] && oj < bestj[r])) {
                bestv[r] = ov; bestj[r] = oj;
            }
        }
    }
    if (tx == 0) {
#pragma unroll
        for (int r = 0; r < 8; r++) {
            g_bv[src][jh][rowTile + ty * 8 + r] = bestv[r];
            g_bj[src][jh][rowTile + ty * 8 + r] = bestj[r];
        }
    }
}

// ---------- kernel 3b: merge the two j-halves ----------
__global__ void combine_kernel(float* __restrict__ out) {
    int i = blockIdx.x * blockDim.x + threadIdx.x;   // 0..131071
    int src = i >> 16;
    int n   = i & (NROWS - 1);
    float v0 = g_bv[src][0][n];
    float v1 = g_bv[src][1][n];
    int   j  = (v1 < v0) ? g_bj[src][1][n] : g_bj[src][0][n];
    out[(src ? OFF_IDXGT : OFF_IDX) + n] = (float)j;
}

// ---------- kernel 4: gather + cosine over H (unchanged) ----------
__global__ void cosine_kernel(const float* __restrict__ cb, float* __restrict__ out) {
    int bw = blockIdx.x;          // 0..1023
    int b  = bw >> 6;
    int w  = bw & 63;
    int c  = threadIdx.x;         // 0..255
    __shared__ int i1s[64], i2s[64];
    const float* f_gt = out + OFF_IDXGT;
    const float* f_z  = out + OFF_IDX;
    if (c < 64) {
        int n = (b << 12) + (c << 6) + w;   // c plays the role of h here
        i1s[c] = (int)f_gt[n];
        i2s[c] = (int)f_z[n];
    }
    __syncthreads();
    float num = 0.f, na = 0.f, nq = 0.f;
    for (int h = 0; h < 64; h++) {
        float a = cb[(size_t)i1s[h] * CDIM + c];
        float q = cb[(size_t)i2s[h] * CDIM + c];
        num = __fadd_rn(num, __fmul_rn(a, q));
        na  = __fadd_rn(na,  __fmul_rn(a, a));
        nq  = __fadd_rn(nq,  __fmul_rn(q, q));
    }
    float nx = fmaxf(__fsqrt_rn(na), 1e-8f);
    float ny = fmaxf(__fsqrt_rn(nq), 1e-8f);
    out[(size_t)bw * CDIM + c] = __fdiv_rn(num, __fmul_rn(nx, ny));
}

extern "C" void kernel_launch(void* const* d_in, const int* in_sizes, int n_in,
                              void* d_out, int out_size) {
    const float* z  = (const float*)d_in[0];
    const float* gt = (const float*)d_in[1];
    const float* cb = (const float*)d_in[2];
    float* out = (float*)d_out;

    cbnorm_kernel<<<128, 256>>>(cb);          // launch 0
    xnorm_kernel<<<2048, 256>>>(z, 0);        // launch 1
    xnorm_kernel<<<2048, 256>>>(gt, 1);       // launch 2
    argmin_kernel<<<dim3(512, 2, 2), 256>>>(z, gt, cb);   // launch 3 (ncu samples idx 3)
    combine_kernel<<<128, 1024>>>(out);       // launch 4
    cosine_kernel<<<NB * NW, CDIM>>>(cb, out);// launch 5
}